// round 4
// baseline (speedup 1.0000x reference)
#include <cuda_runtime.h>
#include <cuda_bf16.h>
#include <cstdint>
#include <math.h>

#define BB 4
#define LL 8192
#define DD 256
#define NLEV 13
#define NOUT 512

// ---------------- scratch (static device globals; no allocation) ----------------
__device__ float g_xt[BB * DD * LL];                 // rmsnorm'd x, (b,d,t) layout
__device__ float g_yt[BB * DD * LL];                 // gelu output, (b,d,t) layout
__device__ __nv_bfloat16 g_yh[(size_t)BB * LL * DD]; // row-major (b*L+t, d), hi
__device__ __nv_bfloat16 g_yl[(size_t)BB * LL * DD]; // lo
__device__ __nv_bfloat16 g_wh[NOUT * DD];            // W^T, columns reordered into GLU pairs, hi
__device__ __nv_bfloat16 g_wl[NOUT * DD];            // lo
__device__ float g_br[NOUT];                         // reordered bias

// ---------------- kernel 0: weight prep (split + transpose + pair-reorder) ------
__global__ void prep_kernel(const float* __restrict__ cw, const float* __restrict__ cb) {
    int idx = blockIdx.x * 256 + threadIdx.x;     // 512 blocks * 256 = 131072 = NOUT*DD
    int n = idx >> 8;                              // reordered column index n' in [0,512)
    int k = idx & 255;
    int oc = (n & 1) ? (DD + (n >> 1)) : (n >> 1); // n'=2i -> i ; n'=2i+1 -> 256+i
    float v = cw[k * NOUT + oc];
    __nv_bfloat16 hi = __float2bfloat16(v);
    float lo = v - __bfloat162float(hi);
    g_wh[n * DD + k] = hi;
    g_wl[n * DD + k] = __float2bfloat16(lo);
    if (idx < NOUT) {
        int occ = (idx & 1) ? (DD + (idx >> 1)) : (idx >> 1);
        g_br[idx] = cb[occ];
    }
}

// ---------------- kernel 1: rmsnorm + transpose to (b,d,t) ----------------------
__global__ void rmsnorm_kernel(const float* __restrict__ x, const float* __restrict__ rs) {
    __shared__ float tile[32][257];
    int b = blockIdx.x >> 8;
    int t0 = (blockIdx.x & 255) * 32;
    int w = threadIdx.x >> 5, lane = threadIdx.x & 31;
    #pragma unroll
    for (int rr = 0; rr < 4; rr++) {
        int tr = w * 4 + rr;
        size_t base = ((size_t)(b * LL + t0 + tr)) * DD;
        float v[8]; float ss = 0.f;
        #pragma unroll
        for (int k = 0; k < 8; k++) { v[k] = x[base + lane + 32 * k]; ss += v[k] * v[k]; }
        #pragma unroll
        for (int o = 16; o > 0; o >>= 1) ss += __shfl_xor_sync(0xffffffffu, ss, o);
        float inv = rsqrtf(ss * (1.f / DD) + 1e-6f);
        #pragma unroll
        for (int k = 0; k < 8; k++) tile[tr][lane + 32 * k] = v[k] * inv * rs[lane + 32 * k];
    }
    __syncthreads();
    #pragma unroll 8
    for (int dd = 0; dd < 32; dd++) {
        int d = w * 32 + dd;
        g_xt[((size_t)(b * DD + d)) * LL + t0 + lane] = tile[lane][d];
    }
}

// ---------------- kernel 2: 13-level dilated depthwise cascade + gelu -----------
__device__ __forceinline__ float gelu_f(float v) {
    float u = 0.7978845608028654f * (v + 0.044715f * v * v * v);
    return 0.5f * v * (1.f + tanhf(u));
}

__global__ void cascade_kernel(const float* __restrict__ h0,
                               const float* __restrict__ h1,
                               const float* __restrict__ wv) {
    extern __shared__ float sb[];
    float* srcb = sb;
    float* dstb = sb + LL;
    int b = blockIdx.x >> 8, d = blockIdx.x & 255;
    float h00 = h0[d * 2], h01 = h0[d * 2 + 1];
    float h10 = h1[d * 2], h11 = h1[d * 2 + 1];
    float w0 = wv[d];
    float wlast = wv[(NLEV + 1) * DD + d];
    size_t base = ((size_t)(b * DD + d)) * LL;
    int tid = threadIdx.x;
    float y[32];
    #pragma unroll
    for (int k = 0; k < 32; k++) {
        int t = tid + 256 * k;
        float v = g_xt[base + t];
        srcb[t] = v;
        y[k] = w0 * v;
    }
    for (int j = 0; j < NLEV; j++) {
        int dil = 1 << j;
        float wj = wv[(j + 1) * DD + d];
        bool last = (j == NLEV - 1);
        __syncthreads();
        #pragma unroll
        for (int k = 0; k < 32; k++) {
            int t = tid + 256 * k;
            float cur = srcb[t];
            float prev = (t >= dil) ? srcb[t - dil] : 0.f;
            y[k] += wj * (h10 * prev + h11 * cur);
            float na = h00 * prev + h01 * cur;
            dstb[t] = na;
            if (last) y[k] += wlast * na;
        }
        float* tmp = srcb; srcb = dstb; dstb = tmp;
    }
    #pragma unroll
    for (int k = 0; k < 32; k++) {
        int t = tid + 256 * k;
        g_yt[base + t] = gelu_f(y[k]);
    }
}

// ---------------- kernel 3: transpose (b,d,t)->(b*L+t,d) + bf16 hi/lo split ----
__global__ void transpose_split_kernel() {
    __shared__ __nv_bfloat16 sh[32][33], sl[32][33];
    int bid = blockIdx.x;             // 4 * 8 * 256 = 8192 blocks
    int b = bid >> 11;
    int rem = bid & 2047;
    int d0 = (rem >> 8) << 5;
    int t0 = (rem & 255) << 5;
    int tl = threadIdx.x & 31, dl8 = threadIdx.x >> 5;
    #pragma unroll
    for (int r = 0; r < 4; r++) {
        int dl = dl8 + r * 8;
        float v = g_yt[((size_t)(b * DD + d0 + dl)) * LL + t0 + tl];
        __nv_bfloat16 hi = __float2bfloat16(v);
        sh[dl][tl] = hi;
        sl[dl][tl] = __float2bfloat16(v - __bfloat162float(hi));
    }
    __syncthreads();
    int dw = threadIdx.x & 31, tw8 = threadIdx.x >> 5;
    #pragma unroll
    for (int r = 0; r < 4; r++) {
        int tw = tw8 + r * 8;
        size_t o = ((size_t)(b * LL + t0 + tw)) * DD + d0 + dw;
        g_yh[o] = sh[dw][tw];
        g_yl[o] = sl[dw][tw];
    }
}

// ---------------- kernel 4: split-bf16 GEMM + bias + GLU + residual -------------
__device__ __forceinline__ void mma16816(float* c, const uint32_t* a, const uint32_t* b) {
    asm volatile(
        "mma.sync.aligned.m16n8k16.row.col.f32.bf16.bf16.f32 "
        "{%0,%1,%2,%3}, {%4,%5,%6,%7}, {%8,%9}, {%0,%1,%2,%3};\n"
        : "+f"(c[0]), "+f"(c[1]), "+f"(c[2]), "+f"(c[3])
        : "r"(a[0]), "r"(a[1]), "r"(a[2]), "r"(a[3]), "r"(b[0]), "r"(b[1]));
}

#define KPAD 40

__global__ void __launch_bounds__(256, 2)
gemm_glu_kernel(const float* __restrict__ xin, float* __restrict__ out) {
    __shared__ __nv_bfloat16 Ah[128][KPAD], Al[128][KPAD];
    __shared__ __nv_bfloat16 Bhs[128][KPAD], Bls[128][KPAD];
    int bid = blockIdx.x;                 // 4 * 64 * 4 = 1024 blocks
    int b = bid >> 8;
    int rem = bid & 255;
    int m0 = (rem >> 2) * 128;
    int n0 = (rem & 3) * 128;
    int tid = threadIdx.x;
    int warp = tid >> 5, lane = tid & 31;
    int wm = warp >> 1, wn = warp & 1;    // 4 x 2 warp grid
    int mb = wm * 32, nb = wn * 64;

    float acc[2][8][4];
    #pragma unroll
    for (int i = 0; i < 2; i++)
        #pragma unroll
        for (int j = 0; j < 8; j++)
            #pragma unroll
            for (int q = 0; q < 4; q++) acc[i][j][q] = 0.f;

    const __nv_bfloat16* Agh = g_yh + ((size_t)b * LL + m0) * DD;
    const __nv_bfloat16* Agl = g_yl + ((size_t)b * LL + m0) * DD;
    const __nv_bfloat16* Bgh = g_wh + (size_t)n0 * DD;
    const __nv_bfloat16* Bgl = g_wl + (size_t)n0 * DD;

    for (int kc = 0; kc < 8; kc++) {
        int k0 = kc * 32;
        __syncthreads();
        #pragma unroll
        for (int rep = 0; rep < 2; rep++) {
            int idx = tid + rep * 256;
            int row = idx >> 2, c4 = idx & 3;
            *(uint4*)&Ah[row][c4 * 8]  = *(const uint4*)&Agh[(size_t)row * DD + k0 + c4 * 8];
            *(uint4*)&Al[row][c4 * 8]  = *(const uint4*)&Agl[(size_t)row * DD + k0 + c4 * 8];
            *(uint4*)&Bhs[row][c4 * 8] = *(const uint4*)&Bgh[(size_t)row * DD + k0 + c4 * 8];
            *(uint4*)&Bls[row][c4 * 8] = *(const uint4*)&Bgl[(size_t)row * DD + k0 + c4 * 8];
        }
        __syncthreads();
        int g = lane >> 2, tg = lane & 3;
        #pragma unroll
        for (int ks = 0; ks < 2; ks++) {
            int kk = ks * 16 + tg * 2;
            uint32_t ah[2][4], al[2][4];
            #pragma unroll
            for (int mi = 0; mi < 2; mi++) {
                int r = mb + mi * 16 + g;
                ah[mi][0] = *(const uint32_t*)&Ah[r][kk];
                ah[mi][1] = *(const uint32_t*)&Ah[r + 8][kk];
                ah[mi][2] = *(const uint32_t*)&Ah[r][kk + 8];
                ah[mi][3] = *(const uint32_t*)&Ah[r + 8][kk + 8];
                al[mi][0] = *(const uint32_t*)&Al[r][kk];
                al[mi][1] = *(const uint32_t*)&Al[r + 8][kk];
                al[mi][2] = *(const uint32_t*)&Al[r][kk + 8];
                al[mi][3] = *(const uint32_t*)&Al[r + 8][kk + 8];
            }
            #pragma unroll
            for (int ni = 0; ni < 8; ni++) {
                int n = nb + ni * 8 + g;
                uint32_t bh[2], bl[2];
                bh[0] = *(const uint32_t*)&Bhs[n][kk];
                bh[1] = *(const uint32_t*)&Bhs[n][kk + 8];
                bl[0] = *(const uint32_t*)&Bls[n][kk];
                bl[1] = *(const uint32_t*)&Bls[n][kk + 8];
                #pragma unroll
                for (int mi = 0; mi < 2; mi++) {
                    mma16816(acc[mi][ni], ah[mi], bh);   // hi*hi
                    mma16816(acc[mi][ni], ah[mi], bl);   // hi*lo
                    mma16816(acc[mi][ni], al[mi], bh);   // lo*hi
                }
            }
        }
    }

    // epilogue: bias + GLU (paired columns) + residual
    int g = lane >> 2, tg = lane & 3;
    #pragma unroll
    for (int mi = 0; mi < 2; mi++) {
        int r0 = m0 + mb + mi * 16 + g;
        #pragma unroll
        for (int ni = 0; ni < 8; ni++) {
            int np = n0 + nb + ni * 8 + tg * 2;  // even reordered column
            float bb0 = g_br[np], bb1 = g_br[np + 1];
            int oc = np >> 1;
            float s0 = acc[mi][ni][0] + bb0;
            float s1 = acc[mi][ni][1] + bb1;
            float s2 = acc[mi][ni][2] + bb0;
            float s3 = acc[mi][ni][3] + bb1;
            size_t o0 = ((size_t)(b * LL + r0)) * DD + oc;
            size_t o1 = ((size_t)(b * LL + r0 + 8)) * DD + oc;
            out[o0] = s0 * (1.f / (1.f + expf(-s1))) + xin[o0];
            out[o1] = s2 * (1.f / (1.f + expf(-s3))) + xin[o1];
        }
    }
}

// ---------------- launch ---------------------------------------------------------
extern "C" void kernel_launch(void* const* d_in, const int* in_sizes, int n_in,
                              void* d_out, int out_size) {
    const float* x  = (const float*)d_in[0];  // (B, L, D)
    const float* rs = (const float*)d_in[1];  // (D,)
    const float* h0 = (const float*)d_in[2];  // (D, 2)
    const float* h1 = (const float*)d_in[3];  // (D, 2)
    const float* wv = (const float*)d_in[4];  // (15, D)
    const float* cw = (const float*)d_in[5];  // (D, 2D)
    const float* cb = (const float*)d_in[6];  // (2D,)
    float* out = (float*)d_out;

    cudaFuncSetAttribute(cascade_kernel, cudaFuncAttributeMaxDynamicSharedMemorySize, 2 * LL * 4);

    prep_kernel<<<512, 256>>>(cw, cb);
    rmsnorm_kernel<<<BB * (LL / 32), 256>>>(x, rs);
    cascade_kernel<<<BB * DD, 256, 2 * LL * 4>>>(h0, h1, wv);
    transpose_split_kernel<<<BB * (DD / 32) * (LL / 32), 256>>>();
    gemm_glu_kernel<<<BB * (LL / 128) * (NOUT / 128), 256>>>(x, out);
}

// round 5
// speedup vs baseline: 1.2543x; 1.2543x over previous
#include <cuda_runtime.h>
#include <cuda_bf16.h>
#include <cuda_fp16.h>
#include <cstdint>
#include <math.h>

#define BB 4
#define LL 8192
#define DD 256
#define NLEV 13
#define NOUT 512

// ---------------- scratch (static device globals; no allocation) ----------------
__device__ float g_xt[BB * DD * LL];       // rmsnorm'd x, (b,d,t) layout
__device__ float g_yt[BB * DD * LL];       // gelu output, (b,d,t) layout
__device__ uint32_t g_whp[NOUT * (DD / 2)]; // W^T reordered into GLU pairs, fp16 k-pair packed
__device__ float g_br[NOUT];               // reordered bias

// ---------------- kernel 0: weight prep (fp16 + transpose + pair-reorder) -------
__global__ void prep_kernel(const float* __restrict__ cw, const float* __restrict__ cb) {
    int idx = blockIdx.x * 256 + threadIdx.x;      // 256 blocks * 256 = 65536 = NOUT*128
    int n = idx >> 7;                               // reordered column index n' in [0,512)
    int kp = idx & 127;
    int k0 = kp * 2;
    int oc = (n & 1) ? (DD + (n >> 1)) : (n >> 1);  // n'=2i -> i ; n'=2i+1 -> 256+i
    float v0 = cw[k0 * NOUT + oc];
    float v1 = cw[(k0 + 1) * NOUT + oc];
    __half2 h = __floats2half2_rn(v0, v1);
    g_whp[n * 128 + kp] = *(uint32_t*)&h;
    if (idx < NOUT) {
        int occ = (idx & 1) ? (DD + (idx >> 1)) : (idx >> 1);
        g_br[idx] = cb[occ];
    }
}

// ---------------- kernel 1: rmsnorm + transpose to (b,d,t) ----------------------
__global__ void rmsnorm_kernel(const float* __restrict__ x, const float* __restrict__ rs) {
    __shared__ float tile[32][257];
    int b = blockIdx.x >> 8;
    int t0 = (blockIdx.x & 255) * 32;
    int w = threadIdx.x >> 5, lane = threadIdx.x & 31;
    #pragma unroll
    for (int rr = 0; rr < 4; rr++) {
        int tr = w * 4 + rr;
        size_t base = ((size_t)(b * LL + t0 + tr)) * DD;
        float v[8]; float ss = 0.f;
        #pragma unroll
        for (int k = 0; k < 8; k++) { v[k] = x[base + lane + 32 * k]; ss += v[k] * v[k]; }
        #pragma unroll
        for (int o = 16; o > 0; o >>= 1) ss += __shfl_xor_sync(0xffffffffu, ss, o);
        float inv = rsqrtf(ss * (1.f / DD) + 1e-6f);
        #pragma unroll
        for (int k = 0; k < 8; k++) tile[tr][lane + 32 * k] = v[k] * inv * rs[lane + 32 * k];
    }
    __syncthreads();
    #pragma unroll 8
    for (int dd = 0; dd < 32; dd++) {
        int d = w * 32 + dd;
        g_xt[((size_t)(b * DD + d)) * LL + t0 + lane] = tile[lane][d];
    }
}

// ---------------- kernel 2: 13-level dilated depthwise cascade + gelu -----------
__device__ __forceinline__ float gelu_f(float v) {
    float u = 0.7978845608028654f * (v + 0.044715f * v * v * v);
    return 0.5f * v * (1.f + tanhf(u));
}

__global__ void __launch_bounds__(256)
cascade_kernel(const float* __restrict__ h0,
               const float* __restrict__ h1,
               const float* __restrict__ wv) {
    extern __shared__ float sb[];
    float* srcb = sb;
    float* dstb = sb + LL;
    int b = blockIdx.x >> 8, d = blockIdx.x & 255;
    float h00 = h0[d * 2], h01 = h0[d * 2 + 1];
    float h10 = h1[d * 2], h11 = h1[d * 2 + 1];
    float w0 = wv[d];
    float wlast = wv[(NLEV + 1) * DD + d];
    size_t base = ((size_t)(b * DD + d)) * LL;
    int tid = threadIdx.x;
    float a[32], y[32];
    #pragma unroll
    for (int k = 0; k < 32; k++) {
        int t = tid + 256 * k;
        a[k] = g_xt[base + t];
        srcb[t] = a[k];
        y[k] = w0 * a[k];
    }
    // levels 0..7: prev lives in another thread -> via smem (1 LDS + 1 STS + 1 sync)
    for (int j = 0; j < 8; j++) {
        int dil = 1 << j;
        float wj = wv[(j + 1) * DD + d];
        __syncthreads();
        #pragma unroll
        for (int k = 0; k < 32; k++) {
            int t = tid + 256 * k;
            float prev = (t >= dil) ? srcb[t - dil] : 0.f;
            y[k] += wj * (h10 * prev + h11 * a[k]);
            a[k] = h00 * prev + h01 * a[k];
            if (j != 7) dstb[t] = a[k];
        }
        float* tmp = srcb; srcb = dstb; dstb = tmp;
    }
    // levels 8..12: dilation = 256*c, prev = a[k-c] in same thread's registers
    #pragma unroll
    for (int j = 8; j < NLEV; j++) {
        int c = 1 << (j - 8);
        float wj = wv[(j + 1) * DD + d];
        #pragma unroll
        for (int k = 31; k >= 0; k--) {
            float prev = (k >= c) ? a[k - c] : 0.f;
            y[k] += wj * (h10 * prev + h11 * a[k]);
            a[k] = h00 * prev + h01 * a[k];
        }
    }
    #pragma unroll
    for (int k = 0; k < 32; k++) {
        int t = tid + 256 * k;
        g_yt[base + t] = gelu_f(y[k] + wlast * a[k]);
    }
}

// ---------------- kernel 3: fused transpose + split-fp16 GEMM + GLU + residual --
__device__ __forceinline__ void mma16816(float* c, const uint32_t* a, const uint32_t* b) {
    asm volatile(
        "mma.sync.aligned.m16n8k16.row.col.f32.f16.f16.f32 "
        "{%0,%1,%2,%3}, {%4,%5,%6,%7}, {%8,%9}, {%0,%1,%2,%3};\n"
        : "+f"(c[0]), "+f"(c[1]), "+f"(c[2]), "+f"(c[3])
        : "r"(a[0]), "r"(a[1]), "r"(a[2]), "r"(a[3]), "r"(b[0]), "r"(b[1]));
}

#define SPITCH 136   // smem row pitch in words; (tg*8 + g) distinct mod 32 -> conflict-free

__global__ void __launch_bounds__(256, 2)
gemm_glu_kernel(const float* __restrict__ xin, float* __restrict__ out) {
    // k-pair-packed fp16: word (kp, m) holds halves (k=2kp, k=2kp+1)
    __shared__ uint32_t sAh[16 * SPITCH];
    __shared__ uint32_t sAl[16 * SPITCH];
    __shared__ uint32_t sB [16 * SPITCH];

    int bid = blockIdx.x;                 // 4 * 64 * 4 = 1024 blocks
    int b = bid >> 8;
    int rem = bid & 255;
    int m0 = (rem >> 2) * 128;
    int n0 = (rem & 3) * 128;
    int tid = threadIdx.x;
    int warp = tid >> 5, lane = tid & 31;
    int wm = warp >> 1, wn = warp & 1;    // 4 x 2 warp grid
    int mb = wm * 32, nb = wn * 64;
    int g = lane >> 2, tg = lane & 3;

    float acc[2][8][4];
    #pragma unroll
    for (int i = 0; i < 2; i++)
        #pragma unroll
        for (int j = 0; j < 8; j++)
            #pragma unroll
            for (int q = 0; q < 4; q++) acc[i][j][q] = 0.f;

    const float* Ag = g_yt + (size_t)b * DD * LL + m0; // index with d*LL + tloc
    int tloc = tid & 127;
    int hf = tid >> 7;

    for (int kc = 0; kc < 8; kc++) {
        __syncthreads();
        // A: read fp32 (d,t) tile coalesced, split to fp16 hi/lo, pack k-pairs
        #pragma unroll
        for (int i = 0; i < 8; i++) {
            int dp = hf * 8 + i;                 // local k-pair 0..15
            int d = kc * 32 + dp * 2;
            float f0 = Ag[(size_t)d * LL + tloc];
            float f1 = Ag[(size_t)(d + 1) * LL + tloc];
            __half hh0 = __float2half_rn(f0);
            __half hh1 = __float2half_rn(f1);
            __half hl0 = __float2half_rn(f0 - __half2float(hh0));
            __half hl1 = __float2half_rn(f1 - __half2float(hh1));
            __half2 ph = __halves2half2(hh0, hh1);
            __half2 pl = __halves2half2(hl0, hl1);
            sAh[dp * SPITCH + tloc] = *(uint32_t*)&ph;
            sAl[dp * SPITCH + tloc] = *(uint32_t*)&pl;
        }
        // B: 8 packed words per thread from row (n0 + tloc)
        {
            const uint4* src = (const uint4*)&g_whp[(size_t)(n0 + tloc) * 128 + kc * 16 + hf * 8];
            uint4 w0 = src[0], w1 = src[1];
            sB[(hf * 8 + 0) * SPITCH + tloc] = w0.x;
            sB[(hf * 8 + 1) * SPITCH + tloc] = w0.y;
            sB[(hf * 8 + 2) * SPITCH + tloc] = w0.z;
            sB[(hf * 8 + 3) * SPITCH + tloc] = w0.w;
            sB[(hf * 8 + 4) * SPITCH + tloc] = w1.x;
            sB[(hf * 8 + 5) * SPITCH + tloc] = w1.y;
            sB[(hf * 8 + 6) * SPITCH + tloc] = w1.z;
            sB[(hf * 8 + 7) * SPITCH + tloc] = w1.w;
        }
        __syncthreads();
        #pragma unroll
        for (int ks = 0; ks < 2; ks++) {
            int kp = ks * 8 + tg;
            uint32_t ah[2][4], al[2][4];
            #pragma unroll
            for (int mi = 0; mi < 2; mi++) {
                int r = mb + mi * 16 + g;
                ah[mi][0] = sAh[kp * SPITCH + r];
                ah[mi][1] = sAh[kp * SPITCH + r + 8];
                ah[mi][2] = sAh[(kp + 4) * SPITCH + r];
                ah[mi][3] = sAh[(kp + 4) * SPITCH + r + 8];
                al[mi][0] = sAl[kp * SPITCH + r];
                al[mi][1] = sAl[kp * SPITCH + r + 8];
                al[mi][2] = sAl[(kp + 4) * SPITCH + r];
                al[mi][3] = sAl[(kp + 4) * SPITCH + r + 8];
            }
            #pragma unroll
            for (int ni = 0; ni < 8; ni++) {
                int n = nb + ni * 8 + g;
                uint32_t bh[2];
                bh[0] = sB[kp * SPITCH + n];
                bh[1] = sB[(kp + 4) * SPITCH + n];
                #pragma unroll
                for (int mi = 0; mi < 2; mi++) {
                    mma16816(acc[mi][ni], ah[mi], bh);   // hi * W
                    mma16816(acc[mi][ni], al[mi], bh);   // lo * W
                }
            }
        }
    }

    // epilogue: bias + GLU (paired columns) + residual
    #pragma unroll
    for (int mi = 0; mi < 2; mi++) {
        int r0 = m0 + mb + mi * 16 + g;
        #pragma unroll
        for (int ni = 0; ni < 8; ni++) {
            int np = n0 + nb + ni * 8 + tg * 2;  // even reordered column
            float bb0 = g_br[np], bb1 = g_br[np + 1];
            int oc = np >> 1;
            float s0 = acc[mi][ni][0] + bb0;
            float s1 = acc[mi][ni][1] + bb1;
            float s2 = acc[mi][ni][2] + bb0;
            float s3 = acc[mi][ni][3] + bb1;
            size_t o0 = ((size_t)(b * LL + r0)) * DD + oc;
            size_t o1 = ((size_t)(b * LL + r0 + 8)) * DD + oc;
            out[o0] = s0 * (1.f / (1.f + __expf(-s1))) + xin[o0];
            out[o1] = s2 * (1.f / (1.f + __expf(-s3))) + xin[o1];
        }
    }
}

// ---------------- launch ---------------------------------------------------------
extern "C" void kernel_launch(void* const* d_in, const int* in_sizes, int n_in,
                              void* d_out, int out_size) {
    const float* x  = (const float*)d_in[0];  // (B, L, D)
    const float* rs = (const float*)d_in[1];  // (D,)
    const float* h0 = (const float*)d_in[2];  // (D, 2)
    const float* h1 = (const float*)d_in[3];  // (D, 2)
    const float* wv = (const float*)d_in[4];  // (15, D)
    const float* cw = (const float*)d_in[5];  // (D, 2D)
    const float* cb = (const float*)d_in[6];  // (2D,)
    float* out = (float*)d_out;

    cudaFuncSetAttribute(cascade_kernel, cudaFuncAttributeMaxDynamicSharedMemorySize, 2 * LL * 4);

    prep_kernel<<<256, 256>>>(cw, cb);
    rmsnorm_kernel<<<BB * (LL / 32), 256>>>(x, rs);
    cascade_kernel<<<BB * DD, 256, 2 * LL * 4>>>(h0, h1, wv);
    gemm_glu_kernel<<<BB * (LL / 128) * (NOUT / 128), 256>>>(x, out);
}